// round 16
// baseline (speedup 1.0000x reference)
#include <cuda_runtime.h>
#include <cuda_fp16.h>
#include <math.h>

#define NN 100000
#define NE 1600000
#define DD 128
#define NG 64
#define JK (3*DD)   // 384

#define NB_SCAN 98          // ceil(NN/1024)
#define XSH 136             // smem row stride in halves (272B -> LDSM conflict-free, 16B-aligned)

// ---------------- scratch (device globals) ----------------
__device__ float  g_dinv[NN];
__device__ int    g_deg[NN];
__device__ int    g_inc[NN];
__device__ int    g_part[NB_SCAN];
__device__ int    g_off[NN + 1];
__device__ int    g_fill[NN];
__device__ uint2  g_meta[NE];                 // {src byte-offset, norm as dup fp16x2}, dst-sorted
__device__ __half g_xh[(size_t)NN*DD];        // fp16 copy of input X
__device__ __half g_wh[3*DD*DD];              // fp16 W1|W2|W3, [k][n] row-major
__device__ __half g_half[(size_t)NN*DD];      // GEMM output messages (fp16)
__device__ __half g_jk[(size_t)NN*JK];        // JK-concat layer outputs (fp16)
__device__ float  g_pooled[NG*JK];
__device__ float  g_cnt[NG];
__device__ float  g_dense[NG*DD];

// ---------------- converts ----------------
__global__ void k_x2h(const float* __restrict__ x) {
    int i = blockIdx.x*256 + threadIdx.x;
    if (i < NN*DD/4) {
        float4 v = ((const float4*)x)[i];
        uint2 hv;
        *(__half2*)&hv.x = __floats2half2_rn(v.x, v.y);
        *(__half2*)&hv.y = __floats2half2_rn(v.z, v.w);
        ((uint2*)g_xh)[i] = hv;
    }
}

__global__ void k_wcvt(const float* __restrict__ W1,
                       const float* __restrict__ W2,
                       const float* __restrict__ W3) {
    int i = blockIdx.x*256 + threadIdx.x;
    int l = i >> 12, j = i & 4095;
    if (l < 3) {
        const float* W = (l == 0) ? W1 : (l == 1) ? W2 : W3;
        float4 v = ((const float4*)W)[j];
        uint2 hv;
        *(__half2*)&hv.x = __floats2half2_rn(v.x, v.y);
        *(__half2*)&hv.y = __floats2half2_rn(v.z, v.w);
        ((uint2*)(g_wh + l*DD*DD))[j] = hv;
    }
}

// ---------------- preprocessing ----------------
__global__ void k_init() {
    int i = blockIdx.x*256 + threadIdx.x;
    if (i < NN) g_deg[i] = 0;
    if (i < NG*JK) g_pooled[i] = 0.0f;
    if (i < NG) g_cnt[i] = 0.0f;
}

__global__ void k_deg(const int* __restrict__ ei) {
    int e = blockIdx.x*256 + threadIdx.x;
    if (e < NE) atomicAdd(&g_deg[ei[NE + e]], 1);
}

// dinv + block-aggregated graph node counts (batch is sorted)
__global__ void k_dinv_cnt(const int* __restrict__ batch) {
    int i = blockIdx.x*256 + threadIdx.x;
    if (i < NN) {
        g_dinv[i] = rsqrtf((float)g_deg[i] + 1.0f);
        int g = batch[i];
        bool start = (threadIdx.x == 0) || (batch[i-1] != g);
        if (start) {
            int end = blockIdx.x*256 + 256;
            if (end > NN) end = NN;
            int c = 0;
            for (int j = i; j < end && batch[j] == g; j++) c++;
            atomicAdd(&g_cnt[g], (float)c);
        }
    }
}

__global__ __launch_bounds__(1024) void k_scan1() {
    __shared__ int sh[1024];
    int t = threadIdx.x;
    int i = blockIdx.x*1024 + t;
    int v = (i < NN) ? g_deg[i] : 0;
    sh[t] = v;
    __syncthreads();
    for (int off = 1; off < 1024; off <<= 1) {
        int add = (t >= off) ? sh[t - off] : 0;
        __syncthreads();
        sh[t] += add;
        __syncthreads();
    }
    if (i < NN) g_inc[i] = sh[t];
    if (t == 1023) g_part[blockIdx.x] = sh[1023];
}

__global__ __launch_bounds__(256) void k_scan23() {
    __shared__ int sp[NB_SCAN];
    __shared__ int pref;
    int t = threadIdx.x;
    if (t < NB_SCAN) sp[t] = g_part[t];
    __syncthreads();
    int b = blockIdx.x >> 2;
    if (t == 0) {
        int run = 0;
        for (int q = 0; q < b; q++) run += sp[q];
        pref = run;
    }
    __syncthreads();
    int i = blockIdx.x*256 + t;
    if (i < NN) {
        int off = g_inc[i] - g_deg[i] + pref;
        g_off[i] = off;
        g_fill[i] = off;
    }
    if (i == 0) g_off[NN] = NE;
}

__global__ void k_reorder(const int* __restrict__ ei) {
    int e = blockIdx.x*256 + threadIdx.x;
    if (e < NE) {
        int s = ei[e];
        int d = ei[NE + e];
        int pos = atomicAdd(&g_fill[d], 1);
        __half nh = __float2half_rn(g_dinv[s] * g_dinv[d]);
        __half2 n2 = __half2half2(nh);
        uint2 m;
        m.x = (unsigned)(s * (DD*2));         // byte offset of source row
        m.y = *(unsigned*)&n2;                // duplicated fp16 norm
        g_meta[pos] = m;
    }
}

// ---------------- fp16 GEMM: cp.async staging + LDSM + HMMA ----------------
__device__ __forceinline__ void cp16(unsigned saddr, const void* gptr) {
    asm volatile("cp.async.cg.shared.global [%0], [%1], 16;" :: "r"(saddr), "l"(gptr));
}

__global__ __launch_bounds__(256, 3) void k_gemm_tc(const __half* __restrict__ Xsrc,
                                                    int xstride,
                                                    const __half* __restrict__ Wsrc) {
    extern __shared__ __half sh[];
    __half* Xs = sh;
    __half* Ws = sh + 128*XSH;

    int t = threadIdx.x;
    int row0 = blockIdx.x * 128;

    unsigned XsA = (unsigned)__cvta_generic_to_shared(Xs);
    unsigned WsA = (unsigned)__cvta_generic_to_shared(Ws);

    #pragma unroll
    for (int j = 0; j < 8; j++) {
        int idx = t + j*256;
        int r = idx >> 4, ch = idx & 15;
        cp16(WsA + (unsigned)((r*XSH + ch*8) * 2), Wsrc + r*DD + ch*8);
    }
    #pragma unroll
    for (int j = 0; j < 8; j++) {
        int idx = t + j*256;
        int r = idx >> 4, ch = idx & 15;
        int row = row0 + r;
        unsigned sa = XsA + (unsigned)((r*XSH + ch*8) * 2);
        if (row < NN) {
            cp16(sa, Xsrc + (size_t)row*xstride + ch*8);
        } else {
            uint4 z = make_uint4(0,0,0,0);
            asm volatile("st.shared.v4.b32 [%0], {%1,%2,%3,%4};"
                         :: "r"(sa), "r"(z.x), "r"(z.y), "r"(z.z), "r"(z.w));
        }
    }
    asm volatile("cp.async.commit_group;");
    asm volatile("cp.async.wait_group 0;");
    __syncthreads();

    int w = t >> 5, lane = t & 31;
    int gid = lane >> 2, tig = lane & 3;
    int rw = (w & 3) * 32;
    int cw = (w >> 2) * 64;
    int l15 = lane & 15;
    int lhi = (lane >> 4) * 8;

    unsigned aAddr0 = XsA + (unsigned)(((rw + l15)*XSH + lhi) * 2);
    unsigned bAddr0 = WsA + (unsigned)((l15*XSH + cw + lhi) * 2);

    float c[2][8][4];
    #pragma unroll
    for (int rt = 0; rt < 2; rt++)
        #pragma unroll
        for (int ct = 0; ct < 8; ct++)
            c[rt][ct][0] = c[rt][ct][1] = c[rt][ct][2] = c[rt][ct][3] = 0.f;

    #pragma unroll
    for (int ks = 0; ks < 8; ks++) {
        unsigned a[2][4], b[8][2];
        #pragma unroll
        for (int rt = 0; rt < 2; rt++) {
            unsigned ad = aAddr0 + rt*(16*XSH*2) + ks*32;
            asm volatile("ldmatrix.sync.aligned.m8n8.x4.shared.b16 {%0,%1,%2,%3}, [%4];"
                         : "=r"(a[rt][0]), "=r"(a[rt][1]), "=r"(a[rt][2]), "=r"(a[rt][3])
                         : "r"(ad));
        }
        #pragma unroll
        for (int pr = 0; pr < 4; pr++) {
            unsigned bd = bAddr0 + ks*(16*XSH*2) + pr*32;
            asm volatile("ldmatrix.sync.aligned.m8n8.x4.trans.shared.b16 {%0,%1,%2,%3}, [%4];"
                         : "=r"(b[2*pr][0]), "=r"(b[2*pr][1]), "=r"(b[2*pr+1][0]), "=r"(b[2*pr+1][1])
                         : "r"(bd));
        }
        #pragma unroll
        for (int rt = 0; rt < 2; rt++)
            #pragma unroll
            for (int ct = 0; ct < 8; ct++) {
                asm volatile(
                    "mma.sync.aligned.m16n8k16.row.col.f32.f16.f16.f32 "
                    "{%0,%1,%2,%3}, {%4,%5,%6,%7}, {%8,%9}, {%0,%1,%2,%3};"
                    : "+f"(c[rt][ct][0]), "+f"(c[rt][ct][1]),
                      "+f"(c[rt][ct][2]), "+f"(c[rt][ct][3])
                    : "r"(a[rt][0]), "r"(a[rt][1]), "r"(a[rt][2]), "r"(a[rt][3]),
                      "r"(b[ct][0]), "r"(b[ct][1]));
            }
    }

    #pragma unroll
    for (int rt = 0; rt < 2; rt++) {
        #pragma unroll
        for (int ct = 0; ct < 8; ct++) {
            int r1 = row0 + rw + rt*16 + gid;
            int col = cw + ct*8 + tig*2;
            if (r1 < NN)
                *(__half2*)(g_half + (size_t)r1*DD + col) = __floats2half2_rn(c[rt][ct][0], c[rt][ct][1]);
            int r2 = r1 + 8;
            if (r2 < NN)
                *(__half2*)(g_half + (size_t)r2*DD + col) = __floats2half2_rn(c[rt][ct][2], c[rt][ct][3]);
        }
    }
}

// ---------------- fused CSR gather: fp16 HFMA2 accumulation + block pooling ----------------
__device__ __forceinline__ __half2 u2h(unsigned u) { return *(__half2*)&u; }

// block = 512 threads = 16 warps = 16 nodes (NN = 6250*16 exactly)
__global__ __launch_bounds__(512, 2) void k_gather(const float* __restrict__ bias,
                                                   const int* __restrict__ batch,
                                                   int off_l) {
    __shared__ float sacc[16*128];
    __shared__ int   sg[16];

    int t = threadIdx.x;
    int wid = t >> 5;
    int lane = t & 31;
    int n = blockIdx.x*16 + wid;

    int e0 = g_off[n];
    int e1 = g_off[n + 1];
    float di = g_dinv[n];

    const char* hbase = (const char*)g_half + lane*8;

    // self loop (fp16 accumulate)
    uint2 sraw = *(const uint2*)(hbase + (size_t)n*(DD*2));
    __half2 w2 = __float2half2_rn(di * di);
    __half2 a0 = __hmul2(w2, u2h(sraw.x));
    __half2 a1 = __hmul2(w2, u2h(sraw.y));

    int e = e0;
    if ((e & 1) && e < e1) {            // peel to 16B-aligned meta pairs
        uint2 m = g_meta[e];
        uint2 r = *(const uint2*)(hbase + m.x);
        __half2 n2 = u2h(m.y);
        a0 = __hfma2(n2, u2h(r.x), a0);
        a1 = __hfma2(n2, u2h(r.y), a1);
        e++;
    }
    for (; e + 8 <= e1; e += 8) {
        uint4 mA = *(const uint4*)(g_meta + e);       // edges e,   e+1
        uint4 mB = *(const uint4*)(g_meta + e + 2);   // edges e+2, e+3
        uint4 mC = *(const uint4*)(g_meta + e + 4);
        uint4 mD = *(const uint4*)(g_meta + e + 6);
        uint2 r0 = *(const uint2*)(hbase + mA.x);
        uint2 r1 = *(const uint2*)(hbase + mA.z);
        uint2 r2 = *(const uint2*)(hbase + mB.x);
        uint2 r3 = *(const uint2*)(hbase + mB.z);
        uint2 r4 = *(const uint2*)(hbase + mC.x);
        uint2 r5 = *(const uint2*)(hbase + mC.z);
        uint2 r6 = *(const uint2*)(hbase + mD.x);
        uint2 r7 = *(const uint2*)(hbase + mD.z);
        a0 = __hfma2(u2h(mA.y), u2h(r0.x), a0);  a1 = __hfma2(u2h(mA.y), u2h(r0.y), a1);
        a0 = __hfma2(u2h(mA.w), u2h(r1.x), a0);  a1 = __hfma2(u2h(mA.w), u2h(r1.y), a1);
        a0 = __hfma2(u2h(mB.y), u2h(r2.x), a0);  a1 = __hfma2(u2h(mB.y), u2h(r2.y), a1);
        a0 = __hfma2(u2h(mB.w), u2h(r3.x), a0);  a1 = __hfma2(u2h(mB.w), u2h(r3.y), a1);
        a0 = __hfma2(u2h(mC.y), u2h(r4.x), a0);  a1 = __hfma2(u2h(mC.y), u2h(r4.y), a1);
        a0 = __hfma2(u2h(mC.w), u2h(r5.x), a0);  a1 = __hfma2(u2h(mC.w), u2h(r5.y), a1);
        a0 = __hfma2(u2h(mD.y), u2h(r6.x), a0);  a1 = __hfma2(u2h(mD.y), u2h(r6.y), a1);
        a0 = __hfma2(u2h(mD.w), u2h(r7.x), a0);  a1 = __hfma2(u2h(mD.w), u2h(r7.y), a1);
    }
    for (; e + 2 <= e1; e += 2) {
        uint4 mA = *(const uint4*)(g_meta + e);
        uint2 r0 = *(const uint2*)(hbase + mA.x);
        uint2 r1 = *(const uint2*)(hbase + mA.z);
        a0 = __hfma2(u2h(mA.y), u2h(r0.x), a0);  a1 = __hfma2(u2h(mA.y), u2h(r0.y), a1);
        a0 = __hfma2(u2h(mA.w), u2h(r1.x), a0);  a1 = __hfma2(u2h(mA.w), u2h(r1.y), a1);
    }
    if (e < e1) {
        uint2 m = g_meta[e];
        uint2 r = *(const uint2*)(hbase + m.x);
        __half2 n2 = u2h(m.y);
        a0 = __hfma2(n2, u2h(r.x), a0);
        a1 = __hfma2(n2, u2h(r.y), a1);
    }

    // epilogue in fp32: bias + relu
    float2 f0 = __half22float2(a0);
    float2 f1 = __half22float2(a1);
    float4 b4 = ((const float4*)bias)[lane];
    float4 acc;
    acc.x = fmaxf(f0.x + b4.x, 0.f);
    acc.y = fmaxf(f0.y + b4.y, 0.f);
    acc.z = fmaxf(f1.x + b4.z, 0.f);
    acc.w = fmaxf(f1.y + b4.w, 0.f);

    uint2 hv;
    *(__half2*)&hv.x = __floats2half2_rn(acc.x, acc.y);
    *(__half2*)&hv.y = __floats2half2_rn(acc.z, acc.w);
    *(uint2*)(g_jk + (size_t)n*JK + off_l + lane*4) = hv;

    // stage for block pooling
    *(float4*)(sacc + wid*128 + lane*4) = acc;
    if (lane == 0) sg[wid] = batch[n];
    __syncthreads();

    // segmented reduction over the 16 nodes (batch sorted -> contiguous runs)
    if (t < 32) {
        float4 run = *(float4*)(sacc + t*4);
        int cur = sg[0];
        #pragma unroll
        for (int r = 1; r < 16; r++) {
            int g = sg[r];
            float4 v = *(float4*)(sacc + r*128 + t*4);
            if (g != cur) {
                float* q = g_pooled + cur*JK + off_l + t*4;
                asm volatile("red.global.add.v4.f32 [%0], {%1,%2,%3,%4};"
                             :: "l"(q), "f"(run.x), "f"(run.y), "f"(run.z), "f"(run.w) : "memory");
                run = v; cur = g;
            } else {
                run.x += v.x; run.y += v.y; run.z += v.z; run.w += v.w;
            }
        }
        float* q = g_pooled + cur*JK + off_l + t*4;
        asm volatile("red.global.add.v4.f32 [%0], {%1,%2,%3,%4};"
                     :: "l"(q), "f"(run.x), "f"(run.y), "f"(run.z), "f"(run.w) : "memory");
    }
}

// ---------------- head ----------------
__global__ __launch_bounds__(128) void k_head1(const float* __restrict__ l1w,
                                               const float* __restrict__ l1b) {
    int g = blockIdx.x;
    int j = threadIdx.x;
    __shared__ float ps[JK];
    float inv = 1.f / fmaxf(g_cnt[g], 1.f);
    for (int k = j; k < JK; k += 128) ps[k] = g_pooled[g*JK + k] * inv;
    __syncthreads();
    float s = l1b[j];
    #pragma unroll 4
    for (int k = 0; k < JK; k++) s = fmaf(ps[k], l1w[k*DD + j], s);
    g_dense[g*DD + j] = fmaxf(s, 0.f);
}

__global__ __launch_bounds__(64) void k_head2(const float* __restrict__ l2w,
                                              const float* __restrict__ l2b,
                                              float* __restrict__ out) {
    __shared__ float ws[DD*10];
    __shared__ float bs[10];
    int t = threadIdx.x;
    for (int i = t; i < DD*10; i += 64) ws[i] = l2w[i];
    if (t < 10) bs[t] = l2b[t];
    __syncthreads();
    if (t < NG) {
        float z[10];
        #pragma unroll
        for (int c = 0; c < 10; c++) z[c] = bs[c];
        for (int k = 0; k < DD; k++) {
            float gv = g_dense[t*DD + k];
            #pragma unroll
            for (int c = 0; c < 10; c++) z[c] = fmaf(gv, ws[k*10 + c], z[c]);
        }
        float m = z[0];
        #pragma unroll
        for (int c = 1; c < 10; c++) m = fmaxf(m, z[c]);
        float ssum = 0.f;
        #pragma unroll
        for (int c = 0; c < 10; c++) ssum += expf(z[c] - m);
        float ls = m + logf(ssum);
        #pragma unroll
        for (int c = 0; c < 10; c++) out[t*10 + c] = z[c] - ls;
    }
}

// ---------------- launch (serial; gemm1 placed 4th for ncu) ----------------
#define GEMM_SMEM (2*128*XSH*2)   // 69632 bytes

extern "C" void kernel_launch(void* const* d_in, const int* in_sizes, int n_in,
                              void* d_out, int out_size) {
    const float* x     = (const float*)d_in[0];
    const int*   ei    = (const int*)  d_in[1];
    const int*   batch = (const int*)  d_in[2];
    const float* W1 = (const float*)d_in[4];  const float* b1 = (const float*)d_in[5];
    const float* W2 = (const float*)d_in[6];  const float* b2 = (const float*)d_in[7];
    const float* W3 = (const float*)d_in[8];  const float* b3 = (const float*)d_in[9];
    const float* l1w = (const float*)d_in[10]; const float* l1b = (const float*)d_in[11];
    const float* l2w = (const float*)d_in[12]; const float* l2b = (const float*)d_in[13];
    float* out = (float*)d_out;

    static int once = 0;
    if (!once) {
        cudaFuncSetAttribute(k_gemm_tc, cudaFuncAttributeMaxDynamicSharedMemorySize, GEMM_SMEM);
        once = 1;
    }

    static __half* d_xh = nullptr;
    static __half* d_wh = nullptr;
    static __half* d_jk = nullptr;
    if (!d_xh) {
        cudaGetSymbolAddress((void**)&d_xh, g_xh);
        cudaGetSymbolAddress((void**)&d_wh, g_wh);
        cudaGetSymbolAddress((void**)&d_jk, g_jk);
    }

    k_x2h     <<<(NN*DD/4 + 255)/256, 256>>>(x);                             // 1
    k_wcvt    <<<(3*4096 + 255)/256, 256>>>(W1, W2, W3);                     // 2
    k_init    <<<(NN + 255)/256, 256>>>();                                   // 3
    k_gemm_tc <<<(NN + 127)/128, 256, GEMM_SMEM>>>(d_xh, DD, d_wh);          // 4 (profiled)
    k_deg     <<<(NE + 255)/256, 256>>>(ei);                                 // 5
    k_dinv_cnt<<<(NN + 255)/256, 256>>>(batch);                              // 6
    k_scan1   <<<NB_SCAN, 1024>>>();                                         // 7
    k_scan23  <<<(NN + 255)/256, 256>>>();                                   // 8
    k_reorder <<<(NE + 255)/256, 256>>>(ei);                                 // 9

    k_gather  <<<NN/16, 512>>>(b1, batch, 0*DD);
    k_gemm_tc <<<(NN + 127)/128, 256, GEMM_SMEM>>>(d_jk + 0*DD, JK, d_wh + 1*DD*DD);
    k_gather  <<<NN/16, 512>>>(b2, batch, 1*DD);
    k_gemm_tc <<<(NN + 127)/128, 256, GEMM_SMEM>>>(d_jk + 1*DD, JK, d_wh + 2*DD*DD);
    k_gather  <<<NN/16, 512>>>(b3, batch, 2*DD);

    k_head1<<<NG, 128>>>(l1w, l1b);
    k_head2<<<1, 64>>>(l2w, l2b, out);
}